// round 3
// baseline (speedup 1.0000x reference)
#include <cuda_runtime.h>

#define BB 2
#define SEQL 2048
#define DD 256
#define HH 8
#define DKK 32
#define DFFN 1024
#define LL 2
#define EPSF 1e-5f

#define NH  (BB*SEQL*DD)      /* 1048576 */
#define NFF (BB*SEQL*DFFN)    /* 4194304 */

__device__ float g_buf[7L*NH + NFF + 512 + 8192];

__device__ __forceinline__ int compute_kcut(float tdh) {
    if (!(tdh > 1e-6f)) return SEQL;
    float c = 128.0f / tdh;
    if (c >= (float)SEQL) return SEQL;
    int k = (int)ceilf(c);
    return k < SEQL ? k : SEQL;
}

// ---------------------------------------------------------------- conv + bn + relu + pe
__global__ void conv_pe_kernel(const float* __restrict__ x, const float* __restrict__ cw,
                               const float* __restrict__ cb, const float* __restrict__ bg,
                               const float* __restrict__ bb, const float* __restrict__ pe,
                               float* __restrict__ out) {
    int idx = blockIdx.x * 256 + threadIdx.x;
    if (idx >= NH) return;
    int d = idx & (DD - 1);
    int t = (idx >> 8) & (SEQL - 1);
    int b = idx >> 19;
    const float* xb = x + b * SEQL;
    float xm = t > 0 ? xb[t - 1] : 0.f;
    float x0 = xb[t];
    float xp = (t < SEQL - 1) ? xb[t + 1] : 0.f;
    float v = cw[d * 3 + 0] * xm + cw[d * 3 + 1] * x0 + cw[d * 3 + 2] * xp + cb[d];
    v = v * rsqrtf(1.f + EPSF) * bg[d] + bb[d];
    v = fmaxf(v, 0.f);
    out[idx] = v + pe[t * DD + d];
}

// ---------------------------------------------------------------- GEMM core (64x64x16 double-buffered, 4x4 micro)
// computes one 64x64 tile of C = A * W^T (+bias), K elements starting at A/W base
template <bool RELU, bool BIAS>
__device__ __forceinline__
void gemm_tile(const float* __restrict__ A, const float* __restrict__ W,
               const float* __restrict__ bias, float* __restrict__ C,
               int m0, int n0, int ldA, int ldW, int N, int K) {
    __shared__ float As[2][16][68];
    __shared__ float Bs[2][16][68];
    const int tid = threadIdx.x;
    const int lr = tid >> 2;
    const int kq = tid & 3;
    const int tx = tid & 15, ty = tid >> 4;

    const float* Ap = A + (long)(m0 + lr) * ldA + kq * 4;
    const float* Bp = W + (long)(n0 + lr) * ldW + kq * 4;

    float4 pa = *(const float4*)(Ap);
    float4 pb = *(const float4*)(Bp);

    float acc[4][4];
#pragma unroll
    for (int i = 0; i < 4; i++)
#pragma unroll
        for (int j = 0; j < 4; j++) acc[i][j] = 0.f;

    As[0][kq * 4 + 0][lr] = pa.x; As[0][kq * 4 + 1][lr] = pa.y;
    As[0][kq * 4 + 2][lr] = pa.z; As[0][kq * 4 + 3][lr] = pa.w;
    Bs[0][kq * 4 + 0][lr] = pb.x; Bs[0][kq * 4 + 1][lr] = pb.y;
    Bs[0][kq * 4 + 2][lr] = pb.z; Bs[0][kq * 4 + 3][lr] = pb.w;
    __syncthreads();

    int s = 0;
    for (int k0 = 16;; k0 += 16) {
        const bool more = (k0 < K);
        if (more) {
            pa = *(const float4*)(Ap + k0);
            pb = *(const float4*)(Bp + k0);
        }
#pragma unroll
        for (int kk = 0; kk < 16; ++kk) {
            float4 av = *(const float4*)&As[s][kk][ty * 4];
            float4 bv = *(const float4*)&Bs[s][kk][tx * 4];
            acc[0][0] = fmaf(av.x, bv.x, acc[0][0]); acc[0][1] = fmaf(av.x, bv.y, acc[0][1]);
            acc[0][2] = fmaf(av.x, bv.z, acc[0][2]); acc[0][3] = fmaf(av.x, bv.w, acc[0][3]);
            acc[1][0] = fmaf(av.y, bv.x, acc[1][0]); acc[1][1] = fmaf(av.y, bv.y, acc[1][1]);
            acc[1][2] = fmaf(av.y, bv.z, acc[1][2]); acc[1][3] = fmaf(av.y, bv.w, acc[1][3]);
            acc[2][0] = fmaf(av.z, bv.x, acc[2][0]); acc[2][1] = fmaf(av.z, bv.y, acc[2][1]);
            acc[2][2] = fmaf(av.z, bv.z, acc[2][2]); acc[2][3] = fmaf(av.z, bv.w, acc[2][3]);
            acc[3][0] = fmaf(av.w, bv.x, acc[3][0]); acc[3][1] = fmaf(av.w, bv.y, acc[3][1]);
            acc[3][2] = fmaf(av.w, bv.z, acc[3][2]); acc[3][3] = fmaf(av.w, bv.w, acc[3][3]);
        }
        if (!more) break;
        const int ns = s ^ 1;
        As[ns][kq * 4 + 0][lr] = pa.x; As[ns][kq * 4 + 1][lr] = pa.y;
        As[ns][kq * 4 + 2][lr] = pa.z; As[ns][kq * 4 + 3][lr] = pa.w;
        Bs[ns][kq * 4 + 0][lr] = pb.x; Bs[ns][kq * 4 + 1][lr] = pb.y;
        Bs[ns][kq * 4 + 2][lr] = pb.z; Bs[ns][kq * 4 + 3][lr] = pb.w;
        __syncthreads();
        s = ns;
    }

    float b0 = 0.f, b1 = 0.f, b2 = 0.f, b3 = 0.f;
    if (BIAS) {
        b0 = bias[n0 + tx * 4 + 0]; b1 = bias[n0 + tx * 4 + 1];
        b2 = bias[n0 + tx * 4 + 2]; b3 = bias[n0 + tx * 4 + 3];
    }
#pragma unroll
    for (int i = 0; i < 4; ++i) {
        float4 v;
        v.x = acc[i][0] + b0; v.y = acc[i][1] + b1;
        v.z = acc[i][2] + b2; v.w = acc[i][3] + b3;
        if (RELU) {
            v.x = fmaxf(v.x, 0.f); v.y = fmaxf(v.y, 0.f);
            v.z = fmaxf(v.z, 0.f); v.w = fmaxf(v.w, 0.f);
        }
        *(float4*)(C + (long)(m0 + ty * 4 + i) * N + n0 + tx * 4) = v;
    }
}

// single GEMM
template <bool RELU>
__global__ __launch_bounds__(256)
void gemm_kernel(const float* __restrict__ A, const float* __restrict__ W,
                 const float* __restrict__ bias, float* __restrict__ C,
                 int M, int N, int K) {
    gemm_tile<RELU, true>(A, W, bias, C, blockIdx.y * 64, blockIdx.x * 64, K, K, N, K);
}

// fused multi-output GEMM: z selects (W, bias, C); shared A. up to 3 outputs.
__global__ __launch_bounds__(256)
void gemm3_kernel(const float* __restrict__ A,
                  const float* __restrict__ W0, const float* __restrict__ W1, const float* __restrict__ W2,
                  const float* __restrict__ b0, const float* __restrict__ b1, const float* __restrict__ b2,
                  float* __restrict__ C0, float* __restrict__ C1, float* __restrict__ C2,
                  int M, int N, int K) {
    int z = blockIdx.z;
    const float* W = (z == 0) ? W0 : (z == 1) ? W1 : W2;
    const float* bi = (z == 0) ? b0 : (z == 1) ? b1 : b2;
    float* C = (z == 0) ? C0 : (z == 1) ? C1 : C2;
    gemm_tile<false, true>(A, W, bi, C, blockIdx.y * 64, blockIdx.x * 64, K, K, N, K);
}

// split-K=2 GEMM: z selects K-half; partial z=0 carries bias, z=1 carries none.
__global__ __launch_bounds__(256)
void gemm_splitk2_kernel(const float* __restrict__ A, const float* __restrict__ W,
                         const float* __restrict__ bias,
                         float* __restrict__ C0, float* __restrict__ C1,
                         int M, int N, int K) {
    int z = blockIdx.z;
    int Kh = K >> 1;
    const float* Ab = A + (long)z * Kh;
    const float* Wb = W + (long)z * Kh;
    float* C = z ? C1 : C0;
    if (z == 0)
        gemm_tile<false, true >(Ab, Wb, bias, C, blockIdx.y * 64, blockIdx.x * 64, K, K, N, Kh);
    else
        gemm_tile<false, false>(Ab, Wb, bias, C, blockIdx.y * 64, blockIdx.x * 64, K, K, N, Kh);
}

// ---------------------------------------------------------------- tail-V
__global__ __launch_bounds__(1024)
void tailv_kernel(const float* __restrict__ V, const float* __restrict__ td,
                  float* __restrict__ tailV, int l) {
    int b = blockIdx.x / HH, h = blockIdx.x % HH;
    float tdh = td[l * HH + h];
    int kcut = compute_kcut(tdh);
    int d = threadIdx.x & 31, kg = threadIdx.x >> 5;
    long base = (long)b * SEQL * DD + h * DKK + d;
    float s0 = 0.f, s1 = 0.f, s2 = 0.f, s3 = 0.f;
    int k = kcut + kg;
    for (; k + 96 < SEQL; k += 128) {
        s0 += V[base + (long)(k      ) * DD];
        s1 += V[base + (long)(k +  32) * DD];
        s2 += V[base + (long)(k +  64) * DD];
        s3 += V[base + (long)(k +  96) * DD];
    }
    for (; k < SEQL; k += 32) s0 += V[base + (long)k * DD];
    float s = (s0 + s1) + (s2 + s3);
    __shared__ float sm[32][33];
    sm[kg][d] = s;
    __syncthreads();
    if (kg == 0) {
        float t = 0.f;
#pragma unroll
        for (int i = 0; i < 32; i++) t += sm[i][d];
        tailV[blockIdx.x * DKK + d] = t;
    }
}

// ---------------------------------------------------------------- attention (all queries), kcut-truncated
__global__ __launch_bounds__(128)
void attn_kernel(const float* __restrict__ Q, const float* __restrict__ Km,
                 const float* __restrict__ Vm, const float* __restrict__ td,
                 const float* __restrict__ scale, const float* __restrict__ tailV,
                 float* __restrict__ ctx, int l) {
    __shared__ float Ks[128][DKK];
    __shared__ float Vs[128][DKK];
    __shared__ float dec[128];
    int bh = blockIdx.y;
    int b = bh / HH, h = bh % HH;
    int tid = threadIdx.x;
    int q = blockIdx.x * 128 + tid;
    float tdh = td[l * HH + h];
    int kcut = compute_kcut(tdh);
    float c = scale[l] * rsqrtf((float)DKK);
    float4 qv[8];
    {
        const float4* qp = (const float4*)(Q + ((long)(b * SEQL + q)) * DD + h * DKK);
#pragma unroll
        for (int j = 0; j < 8; ++j) {
            float4 t = qp[j];
            t.x *= c; t.y *= c; t.z *= c; t.w *= c;
            qv[j] = t;
        }
    }
    float Z = 0.f;
    float4 cx[8];
#pragma unroll
    for (int j = 0; j < 8; ++j) cx[j] = make_float4(0.f, 0.f, 0.f, 0.f);

    for (int kb = 0; kb < kcut; kb += 128) {
        int kn = min(128, kcut - kb);
        __syncthreads();
        const float4* Kg = (const float4*)(Km + ((long)(b * SEQL + kb)) * DD + h * DKK);
        const float4* Vg = (const float4*)(Vm + ((long)(b * SEQL + kb)) * DD + h * DKK);
#pragma unroll
        for (int i = 0; i < 8; i++) {
            int idx = i * 128 + tid;
            int r = idx >> 3, c4 = idx & 7;
            if (r < kn) {
                ((float4*)Ks[r])[c4] = Kg[(long)r * (DD / 4) + c4];
                ((float4*)Vs[r])[c4] = Vg[(long)r * (DD / 4) + c4];
            }
        }
        if (tid < kn) dec[tid] = __expf(-tdh * (float)(kb + tid));
        __syncthreads();
        for (int kk = 0; kk < kn; ++kk) {
            const float4* kr = (const float4*)Ks[kk];
            float s0 = 0.f, s1 = 0.f, s2 = 0.f, s3 = 0.f;
#pragma unroll
            for (int j = 0; j < 8; j += 2) {
                float4 k0 = kr[j], k1 = kr[j + 1];
                s0 = fmaf(qv[j].x, k0.x, s0); s1 = fmaf(qv[j].y, k0.y, s1);
                s2 = fmaf(qv[j].z, k0.z, s2); s3 = fmaf(qv[j].w, k0.w, s3);
                s0 = fmaf(qv[j + 1].x, k1.x, s0); s1 = fmaf(qv[j + 1].y, k1.y, s1);
                s2 = fmaf(qv[j + 1].z, k1.z, s2); s3 = fmaf(qv[j + 1].w, k1.w, s3);
            }
            float s = ((s0 + s1) + (s2 + s3)) * dec[kk];
            float e = __expf(s);
            float w = e * e / (1.f + e);
            Z += e;
            const float4* vr = (const float4*)Vs[kk];
#pragma unroll
            for (int j = 0; j < 8; ++j) {
                float4 vv = vr[j];
                cx[j].x = fmaf(w, vv.x, cx[j].x);
                cx[j].y = fmaf(w, vv.y, cx[j].y);
                cx[j].z = fmaf(w, vv.z, cx[j].z);
                cx[j].w = fmaf(w, vv.w, cx[j].w);
            }
        }
    }
    Z += (float)(SEQL - kcut);
    float invZ = 1.f / Z;
    const float4* tv = (const float4*)(tailV + bh * DKK);
    float4* op = (float4*)(ctx + ((long)(b * SEQL + q)) * DD + h * DKK);
#pragma unroll
    for (int j = 0; j < 8; ++j) {
        float4 t = tv[j];
        float4 o;
        o.x = (cx[j].x + 0.5f * t.x) * invZ;
        o.y = (cx[j].y + 0.5f * t.y) * invZ;
        o.z = (cx[j].z + 0.5f * t.z) * invZ;
        o.w = (cx[j].w + 0.5f * t.w) * invZ;
        op[j] = o;
    }
}

// ---------------------------------------------------------------- single-query attention (layer 2 last token)
__global__ __launch_bounds__(128)
void attn1_kernel(const float* __restrict__ q2, const float* __restrict__ Km,
                  const float* __restrict__ Vm, const float* __restrict__ td,
                  const float* __restrict__ scale, const float* __restrict__ tailV,
                  float* __restrict__ ctx2, int l) {
    int b = blockIdx.x / HH, h = blockIdx.x % HH;
    int tid = threadIdx.x;
    float tdh = td[l * HH + h];
    int kcut = compute_kcut(tdh);
    float c = scale[l] * rsqrtf((float)DKK);
    __shared__ float qs[DKK];
    __shared__ float ws[128];
    __shared__ float red[4];
    if (tid < DKK) qs[tid] = q2[b * DD + h * DKK + tid] * c;
    __syncthreads();
    float Zp = 0.f;
    float cxd = 0.f;
    for (int kb = 0; kb < kcut; kb += 128) {
        int kn = min(128, kcut - kb);
        float w = 0.f;
        if (tid < kn) {
            int k = kb + tid;
            const float* kr = Km + ((long)(b * SEQL + k)) * DD + h * DKK;
            float s = 0.f;
#pragma unroll
            for (int d = 0; d < DKK; ++d) s = fmaf(qs[d], kr[d], s);
            s *= __expf(-tdh * (float)k);
            float e = __expf(s);
            w = e * e / (1.f + e);
            Zp += e;
        }
        __syncthreads();
        ws[tid] = w;
        __syncthreads();
        if (tid < DKK) {
            for (int kk = 0; kk < kn; ++kk)
                cxd = fmaf(ws[kk], Vm[((long)(b * SEQL + kb + kk)) * DD + h * DKK + tid], cxd);
        }
        __syncthreads();
    }
    float s = Zp;
#pragma unroll
    for (int o = 16; o; o >>= 1) s += __shfl_xor_sync(0xffffffffu, s, o);
    if ((tid & 31) == 0) red[tid >> 5] = s;
    __syncthreads();
    float Z = red[0] + red[1] + red[2] + red[3] + (float)(SEQL - kcut);
    if (tid < DKK)
        ctx2[b * DD + h * DKK + tid] = (cxd + 0.5f * tailV[blockIdx.x * DKK + tid]) / Z;
}

// ---------------------------------------------------------------- small-M GEMM (M=2 rows)
template <bool RELU>
__global__ void rowgemm_kernel(const float* __restrict__ A, long lda,
                               const float* __restrict__ W, const float* __restrict__ bias,
                               float* __restrict__ C, int K, int N) {
    extern __shared__ float arow[];
    int m = blockIdx.x;
    int n = blockIdx.y * blockDim.x + threadIdx.x;
    for (int i = threadIdx.x; i < K; i += blockDim.x) arow[i] = A[(long)m * lda + i];
    __syncthreads();
    float s = bias[n];
    const float* wr = W + (long)n * K;
#pragma unroll 4
    for (int kk = 0; kk < K; ++kk) s = fmaf(arow[kk], wr[kk], s);
    if (RELU) s = fmaxf(s, 0.f);
    C[(long)m * N + n] = s;
}

// ---------------------------------------------------------------- residual + layernorm; optional 2nd partial
template <bool TWO>
__global__ void ln_kernel(const float* __restrict__ z, long zs,
                          const float* __restrict__ z2,
                          const float* __restrict__ res, long rs,
                          const float* __restrict__ g, const float* __restrict__ be,
                          float* __restrict__ out, long os) {
    int m = blockIdx.x, t = threadIdx.x;
    float v = z[(long)m * zs + t] + res[(long)m * rs + t];
    if (TWO) v += z2[(long)m * zs + t];
    __shared__ float sm[8];
    float s = v;
#pragma unroll
    for (int o = 16; o; o >>= 1) s += __shfl_xor_sync(0xffffffffu, s, o);
    if ((t & 31) == 0) sm[t >> 5] = s;
    __syncthreads();
    float tot = 0.f;
#pragma unroll
    for (int i = 0; i < 8; i++) tot += sm[i];
    float mean = tot * (1.0f / DD);
    float dv = v - mean;
    float s2 = dv * dv;
    __syncthreads();
#pragma unroll
    for (int o = 16; o; o >>= 1) s2 += __shfl_xor_sync(0xffffffffu, s2, o);
    if ((t & 31) == 0) sm[t >> 5] = s2;
    __syncthreads();
    float var = 0.f;
#pragma unroll
    for (int i = 0; i < 8; i++) var += sm[i];
    var *= (1.0f / DD);
    out[(long)m * os + t] = dv * rsqrtf(var + EPSF) * g[t] + be[t];
}

// ---------------------------------------------------------------- final projection
__global__ void out_kernel(const float* __restrict__ r2, const float* __restrict__ ow,
                           const float* __restrict__ ob, float* __restrict__ out) {
    int b = blockIdx.x, t = threadIdx.x;
    float p = r2[b * DD + t] * ow[t];
    __shared__ float sm[8];
    float s = p;
#pragma unroll
    for (int o = 16; o; o >>= 1) s += __shfl_xor_sync(0xffffffffu, s, o);
    if ((t & 31) == 0) sm[t >> 5] = s;
    __syncthreads();
    if (t == 0) {
        float tot = 0.f;
#pragma unroll
        for (int i = 0; i < 8; i++) tot += sm[i];
        out[b] = 0.5f * tot + ob[0];
    }
}

// ================================================================ host orchestration
extern "C" void kernel_launch(void* const* d_in, const int* in_sizes, int n_in,
                              void* d_out, int out_size) {
    const float* x   = (const float*)d_in[0];
    const float* cw  = (const float*)d_in[1];
    const float* cb  = (const float*)d_in[2];
    const float* bg  = (const float*)d_in[3];
    const float* bbn = (const float*)d_in[4];
    const float* pe  = (const float*)d_in[5];
    const float* qW  = (const float*)d_in[6];
    const float* qb  = (const float*)d_in[7];
    const float* kW  = (const float*)d_in[8];
    const float* kb  = (const float*)d_in[9];
    const float* vW  = (const float*)d_in[10];
    const float* vb  = (const float*)d_in[11];
    const float* oW  = (const float*)d_in[12];
    const float* ob  = (const float*)d_in[13];
    const float* scale = (const float*)d_in[14];
    const float* td  = (const float*)d_in[15];
    const float* ln1g = (const float*)d_in[16];
    const float* ln1b = (const float*)d_in[17];
    const float* f1W = (const float*)d_in[18];
    const float* f1b = (const float*)d_in[19];
    const float* f2W = (const float*)d_in[20];
    const float* f2b = (const float*)d_in[21];
    const float* ln2g = (const float*)d_in[22];
    const float* ln2b = (const float*)d_in[23];
    const float* outW = (const float*)d_in[24];
    const float* outb = (const float*)d_in[25];
    float* out = (float*)d_out;

    float* buf = nullptr;
    cudaGetSymbolAddress((void**)&buf, g_buf);
    float* H0   = buf;
    float* H2   = buf + 1L * NH;
    float* Qb   = buf + 2L * NH;
    float* Kb   = buf + 3L * NH;
    float* Vb   = buf + 4L * NH;
    float* CTX  = buf + 5L * NH;
    float* T    = buf + 6L * NH;
    float* FF   = buf + 7L * NH;
    float* TAIL = buf + 7L * NH + NFF;
    float* SM   = TAIL + 512;
    float* Q2    = SM + 0;
    float* CTX2  = SM + 512;
    float* T2    = SM + 1024;
    float* R1    = SM + 1536;
    float* FFROW = SM + 2048;
    float* T3    = SM + 4096;
    float* R2    = SM + 4608;

    const int M = BB * SEQL;                      // 4096
    dim3 gQKV(DD / 64, M / 64, 3);                // 768 CTAs
    dim3 gKV(DD / 64, M / 64, 2);                 // 512 CTAs
    dim3 gN256(DD / 64, M / 64);                  // 256 CTAs
    dim3 gN1024(DFFN / 64, M / 64);               // 1024 CTAs
    dim3 gSK2(DD / 64, M / 64, 2);                // 512 CTAs
    dim3 gAttn(SEQL / 128, BB * HH);              // 256 CTAs

    // --- stem ---
    conv_pe_kernel<<<(NH + 255) / 256, 256>>>(x, cw, cb, bg, bbn, pe, H0);

    // --- layer 0 (full) ---
    gemm3_kernel<<<gQKV, 256>>>(H0, qW, kW, vW, qb, kb, vb, Qb, Kb, Vb, M, DD, DD);
    tailv_kernel<<<BB * HH, 1024>>>(Vb, td, TAIL, 0);
    attn_kernel<<<gAttn, 128>>>(Qb, Kb, Vb, td, scale, TAIL, CTX, 0);
    gemm_kernel<false><<<gN256, 256>>>(CTX, oW, ob, T, M, DD, DD);
    ln_kernel<false><<<M, 256>>>(T, DD, nullptr, H0, DD, ln1g, ln1b, H2, DD);
    gemm_kernel<true ><<<gN1024, 256>>>(H2, f1W, f1b, FF, M, DFFN, DD);
    // FFN2 split-K=2: partials into T (with bias) and Qb (no bias), summed in LN
    gemm_splitk2_kernel<<<gSK2, 256>>>(FF, f2W, f2b, T, Qb, M, DD, DFFN);
    ln_kernel<true ><<<M, 256>>>(T, DD, Qb, H2, DD, ln2g, ln2b, H0, DD);

    // --- layer 1 (only last token needed downstream of attention) ---
    const float* qW1 = qW + DD * DD;   const float* qb1 = qb + DD;
    const float* kW1 = kW + DD * DD;   const float* kb1 = kb + DD;
    const float* vW1 = vW + DD * DD;   const float* vb1 = vb + DD;
    const float* oW1 = oW + DD * DD;   const float* ob1 = ob + DD;
    const float* ln1g1 = ln1g + DD;    const float* ln1b1 = ln1b + DD;
    const float* ln2g1 = ln2g + DD;    const float* ln2b1 = ln2b + DD;
    const float* f1W1 = f1W + DFFN * DD; const float* f1b1 = f1b + DFFN;
    const float* f2W1 = f2W + DD * DFFN; const float* f2b1 = f2b + DD;
    const float* hlast = H0 + (long)(SEQL - 1) * DD;

    gemm3_kernel<<<gKV, 256>>>(H0, kW1, vW1, nullptr, kb1, vb1, nullptr, Kb, Vb, nullptr, M, DD, DD);
    tailv_kernel<<<BB * HH, 1024>>>(Vb, td, TAIL, 1);

    rowgemm_kernel<false><<<dim3(BB, 1), 256, DD * 4>>>(hlast, (long)SEQL * DD, qW1, qb1, Q2, DD, DD);
    attn1_kernel<<<BB * HH, 128>>>(Q2, Kb, Vb, td, scale, TAIL, CTX2, 1);
    rowgemm_kernel<false><<<dim3(BB, 1), 256, DD * 4>>>(CTX2, DD, oW1, ob1, T2, DD, DD);
    ln_kernel<false><<<BB, 256>>>(T2, DD, nullptr, hlast, (long)SEQL * DD, ln1g1, ln1b1, R1, DD);
    rowgemm_kernel<true ><<<dim3(BB, DFFN / 256), 256, DD * 4>>>(R1, DD, f1W1, f1b1, FFROW, DD, DFFN);
    rowgemm_kernel<false><<<dim3(BB, 1), 256, DFFN * 4>>>(FFROW, DFFN, f2W1, f2b1, T3, DFFN, DD);
    ln_kernel<false><<<BB, 256>>>(T3, DD, nullptr, R1, DD, ln2g1, ln2b1, R2, DD);

    out_kernel<<<BB, 256>>>(R2, outW, outb, out);
}

// round 5
// speedup vs baseline: 1.2934x; 1.2934x over previous
#include <cuda_runtime.h>
#include <cuda_bf16.h>

#define BB 2
#define SEQL 2048
#define DD 256
#define HH 8
#define DKK 32
#define DFFN 1024
#define EPSF 1e-5f

#define NH  (BB*SEQL*DD)      /* 1048576 */
#define NFF (BB*SEQL*DFFN)    /* 4194304 */

// fp32: H0,H2,Qb,Kb,Vb,T,TP = 7*NH
// bf16 region: 6*NH + 2*NFF activations + 3145728 weights = 17825792 bf16 = 8912896 floats
#define BF16_FLOATS 8912896L
__device__ float g_buf[7L*NH + BF16_FLOATS + 512 + 8192];

__device__ __forceinline__ int compute_kcut(float tdh) {
    if (!(tdh > 1e-6f)) return SEQL;
    float c = 33.0f / tdh;     // exp(s * e^-33) == 1.0f exactly for |s| < 1e7
    if (c >= (float)SEQL) return SEQL;
    int k = (int)ceilf(c);
    return k < SEQL ? k : SEQL;
}

// ---------------------------------------------------------------- conv + bn + relu + pe (+ bf16 split)
__global__ void conv_pe_kernel(const float* __restrict__ x, const float* __restrict__ cw,
                               const float* __restrict__ cb, const float* __restrict__ bg,
                               const float* __restrict__ bb, const float* __restrict__ pe,
                               float* __restrict__ out,
                               __nv_bfloat16* __restrict__ oh, __nv_bfloat16* __restrict__ ol) {
    int idx = blockIdx.x * 256 + threadIdx.x;
    if (idx >= NH) return;
    int d = idx & (DD - 1);
    int t = (idx >> 8) & (SEQL - 1);
    int b = idx >> 19;
    const float* xb = x + b * SEQL;
    float xm = t > 0 ? xb[t - 1] : 0.f;
    float x0 = xb[t];
    float xp = (t < SEQL - 1) ? xb[t + 1] : 0.f;
    float v = cw[d * 3 + 0] * xm + cw[d * 3 + 1] * x0 + cw[d * 3 + 2] * xp + cb[d];
    v = v * rsqrtf(1.f + EPSF) * bg[d] + bb[d];
    v = fmaxf(v, 0.f);
    float r = v + pe[t * DD + d];
    out[idx] = r;
    __nv_bfloat16 h = __float2bfloat16(r);
    oh[idx] = h;
    ol[idx] = __float2bfloat16(r - __bfloat162float(h));
}

// ---------------------------------------------------------------- weight split fp32 -> bf16 hi/lo
__global__ void wsplit_kernel(const float* __restrict__ q, const float* __restrict__ k,
                              const float* __restrict__ v, const float* __restrict__ o,
                              const float* __restrict__ f1, const float* __restrict__ f2,
                              __nv_bfloat16* __restrict__ W) {
    int z = blockIdx.z;
    const float* src; long n; long off;
    switch (z) {
        case 0: src = q;  n = 131072; off = 0;       break;
        case 1: src = k;  n = 131072; off = 262144;  break;
        case 2: src = v;  n = 131072; off = 524288;  break;
        case 3: src = o;  n = 131072; off = 786432;  break;
        case 4: src = f1; n = 524288; off = 1048576; break;
        default: src = f2; n = 524288; off = 2097152; break;
    }
    __nv_bfloat16* dh = W + off;
    __nv_bfloat16* dl = dh + n;
    for (long i = blockIdx.x * 256L + threadIdx.x; i < n; i += (long)gridDim.x * 256L) {
        float xx = src[i];
        __nv_bfloat16 h = __float2bfloat16(xx);
        dh[i] = h;
        dl[i] = __float2bfloat16(xx - __bfloat162float(h));
    }
}

// ---------------------------------------------------------------- HMMA GEMM: C[M,N] = A[M,K] @ W[N,K]^T
// A, W as bf16 hi/lo split; fp32 accumulate; 3 cross-term passes (hh, hl, lh).
struct TcJob {
    const __nv_bfloat16 *Ah, *Al;
    const __nv_bfloat16 *Wh, *Wl;
    const float* bias;
    float* C;
    __nv_bfloat16 *Ch, *Cl;
    int lda, ldw, N, K, flags;   // flags: 1=RELU 2=FP32OUT 4=BF16OUT 8=BIAS
};
struct TcJobs3 { TcJob j[3]; };

#define MMA_BF16(c, a, b) \
    asm volatile("mma.sync.aligned.m16n8k16.row.col.f32.bf16.bf16.f32 " \
        "{%0,%1,%2,%3}, {%4,%5,%6,%7}, {%8,%9}, {%0,%1,%2,%3};" \
        : "+f"((c)[0]), "+f"((c)[1]), "+f"((c)[2]), "+f"((c)[3]) \
        : "r"((a)[0]), "r"((a)[1]), "r"((a)[2]), "r"((a)[3]), "r"((b)[0]), "r"((b)[1]))

#define LDU(p) (*(const unsigned*)(p))

__global__ __launch_bounds__(256) void tc_kernel(TcJobs3 jobs) {
    TcJob jb = jobs.j[blockIdx.z];
    __shared__ __nv_bfloat16 sA[2][128][40];   // [hi/lo][row][k+pad]
    __shared__ __nv_bfloat16 sB[2][64][40];
    const int tid = threadIdx.x, wid = tid >> 5, lane = tid & 31;
    const int m0 = blockIdx.y * 128, n0 = blockIdx.x * 64;
    const int wm = (wid & 3) * 32, wn = (wid >> 2) * 32;
    const int g = lane >> 2, tg = lane & 3;

    float acc[2][4][4];
#pragma unroll
    for (int mi = 0; mi < 2; mi++)
#pragma unroll
        for (int ni = 0; ni < 4; ni++)
#pragma unroll
            for (int r = 0; r < 4; r++) acc[mi][ni][r] = 0.f;

    const int arow = (tid * 2) >> 3, ac8 = (tid * 2) & 7;      // A: idx pairs
    const int brow = tid >> 2, bc8 = tid & 3;                  // B: one uint4 each

    for (int kb = 0; kb < jb.K; kb += 32) {
        // ---- global -> regs (A: 128x32 hi+lo; B: 64x32 hi+lo) ----
        uint4 ra_h[2], ra_l[2], rb_h, rb_l;
#pragma unroll
        for (int i = 0; i < 2; i++) {
            int idx = i * 256 + tid;             // 512 uint4 over A tile
            int rr = idx >> 2, cc = idx & 3;
            size_t go = (size_t)(m0 + rr) * jb.lda + kb + cc * 8;
            ra_h[i] = *(const uint4*)(jb.Ah + go);
            ra_l[i] = *(const uint4*)(jb.Al + go);
        }
        {
            size_t go = (size_t)(n0 + brow) * jb.ldw + kb + bc8 * 8;
            rb_h = *(const uint4*)(jb.Wh + go);
            rb_l = *(const uint4*)(jb.Wl + go);
        }
        __syncthreads();
#pragma unroll
        for (int i = 0; i < 2; i++) {
            int idx = i * 256 + tid;
            int rr = idx >> 2, cc = idx & 3;
            *(uint4*)&sA[0][rr][cc * 8] = ra_h[i];
            *(uint4*)&sA[1][rr][cc * 8] = ra_l[i];
        }
        *(uint4*)&sB[0][brow][bc8 * 8] = rb_h;
        *(uint4*)&sB[1][brow][bc8 * 8] = rb_l;
        __syncthreads();

        // ---- compute: 2 k16 steps ----
#pragma unroll
        for (int ks = 0; ks < 2; ks++) {
            const int k0 = ks * 16;
            unsigned ah[2][4], al[2][4];
#pragma unroll
            for (int mi = 0; mi < 2; mi++) {
                int r = wm + mi * 16 + g;
                ah[mi][0] = LDU(&sA[0][r][k0 + 2 * tg]);
                ah[mi][1] = LDU(&sA[0][r + 8][k0 + 2 * tg]);
                ah[mi][2] = LDU(&sA[0][r][k0 + 2 * tg + 8]);
                ah[mi][3] = LDU(&sA[0][r + 8][k0 + 2 * tg + 8]);
                al[mi][0] = LDU(&sA[1][r][k0 + 2 * tg]);
                al[mi][1] = LDU(&sA[1][r + 8][k0 + 2 * tg]);
                al[mi][2] = LDU(&sA[1][r][k0 + 2 * tg + 8]);
                al[mi][3] = LDU(&sA[1][r + 8][k0 + 2 * tg + 8]);
            }
            unsigned bh[4][2], bl[4][2];
#pragma unroll
            for (int ni = 0; ni < 4; ni++) {
                int rn = wn + ni * 8 + g;
                bh[ni][0] = LDU(&sB[0][rn][k0 + 2 * tg]);
                bh[ni][1] = LDU(&sB[0][rn][k0 + 2 * tg + 8]);
                bl[ni][0] = LDU(&sB[1][rn][k0 + 2 * tg]);
                bl[ni][1] = LDU(&sB[1][rn][k0 + 2 * tg + 8]);
            }
#pragma unroll
            for (int mi = 0; mi < 2; mi++)
#pragma unroll
                for (int ni = 0; ni < 4; ni++) {
                    MMA_BF16(acc[mi][ni], ah[mi], bh[ni]);
                    MMA_BF16(acc[mi][ni], ah[mi], bl[ni]);
                    MMA_BF16(acc[mi][ni], al[mi], bh[ni]);
                }
        }
    }

    // ---- epilogue ----
    const bool hasb = (jb.flags & 8), rl = (jb.flags & 1);
#pragma unroll
    for (int mi = 0; mi < 2; mi++) {
#pragma unroll
        for (int ni = 0; ni < 4; ni++) {
            int r0 = m0 + wm + mi * 16 + g;
            int r1 = r0 + 8;
            int cb = n0 + wn + ni * 8 + 2 * tg;
            float v0 = acc[mi][ni][0], v1 = acc[mi][ni][1];
            float v2 = acc[mi][ni][2], v3 = acc[mi][ni][3];
            if (hasb) {
                float b0 = jb.bias[cb], b1 = jb.bias[cb + 1];
                v0 += b0; v1 += b1; v2 += b0; v3 += b1;
            }
            if (rl) {
                v0 = fmaxf(v0, 0.f); v1 = fmaxf(v1, 0.f);
                v2 = fmaxf(v2, 0.f); v3 = fmaxf(v3, 0.f);
            }
            if (jb.flags & 2) {
                *(float2*)(jb.C + (size_t)r0 * jb.N + cb) = make_float2(v0, v1);
                *(float2*)(jb.C + (size_t)r1 * jb.N + cb) = make_float2(v2, v3);
            }
            if (jb.flags & 4) {
                __nv_bfloat162 h0, l0, h1, l1;
                h0.x = __float2bfloat16(v0); h0.y = __float2bfloat16(v1);
                l0.x = __float2bfloat16(v0 - __bfloat162float(h0.x));
                l0.y = __float2bfloat16(v1 - __bfloat162float(h0.y));
                h1.x = __float2bfloat16(v2); h1.y = __float2bfloat16(v3);
                l1.x = __float2bfloat16(v2 - __bfloat162float(h1.x));
                l1.y = __float2bfloat16(v3 - __bfloat162float(h1.y));
                *(__nv_bfloat162*)(jb.Ch + (size_t)r0 * jb.N + cb) = h0;
                *(__nv_bfloat162*)(jb.Cl + (size_t)r0 * jb.N + cb) = l0;
                *(__nv_bfloat162*)(jb.Ch + (size_t)r1 * jb.N + cb) = h1;
                *(__nv_bfloat162*)(jb.Cl + (size_t)r1 * jb.N + cb) = l1;
            }
        }
    }
}

// ---------------------------------------------------------------- tail-V
__global__ __launch_bounds__(1024)
void tailv_kernel(const float* __restrict__ V, const float* __restrict__ td,
                  float* __restrict__ tailV, int l) {
    int b = blockIdx.x / HH, h = blockIdx.x % HH;
    float tdh = td[l * HH + h];
    int kcut = compute_kcut(tdh);
    int d = threadIdx.x & 31, kg = threadIdx.x >> 5;
    long base = (long)b * SEQL * DD + h * DKK + d;
    float s0 = 0.f, s1 = 0.f, s2 = 0.f, s3 = 0.f;
    int k = kcut + kg;
    for (; k + 96 < SEQL; k += 128) {
        s0 += V[base + (long)(k      ) * DD];
        s1 += V[base + (long)(k +  32) * DD];
        s2 += V[base + (long)(k +  64) * DD];
        s3 += V[base + (long)(k +  96) * DD];
    }
    for (; k < SEQL; k += 32) s0 += V[base + (long)k * DD];
    float s = (s0 + s1) + (s2 + s3);
    __shared__ float sm[32][33];
    sm[kg][d] = s;
    __syncthreads();
    if (kg == 0) {
        float t = 0.f;
#pragma unroll
        for (int i = 0; i < 32; i++) t += sm[i][d];
        tailV[blockIdx.x * DKK + d] = t;
    }
}

// ---------------------------------------------------------------- attention (emits bf16 hi/lo ctx)
__global__ __launch_bounds__(128)
void attn_kernel(const float* __restrict__ Q, const float* __restrict__ Km,
                 const float* __restrict__ Vm, const float* __restrict__ td,
                 const float* __restrict__ scale, const float* __restrict__ tailV,
                 __nv_bfloat16* __restrict__ Ch, __nv_bfloat16* __restrict__ Cl, int l) {
    __shared__ float Ks[128][DKK];
    __shared__ float Vs[128][DKK];
    __shared__ float dec[128];
    int bh = blockIdx.y;
    int b = bh / HH, h = bh % HH;
    int tid = threadIdx.x;
    int q = blockIdx.x * 128 + tid;
    float tdh = td[l * HH + h];
    int kcut = compute_kcut(tdh);
    float c = scale[l] * rsqrtf((float)DKK);
    float4 qv[8];
    {
        const float4* qp = (const float4*)(Q + ((long)(b * SEQL + q)) * DD + h * DKK);
#pragma unroll
        for (int j = 0; j < 8; ++j) {
            float4 t = qp[j];
            t.x *= c; t.y *= c; t.z *= c; t.w *= c;
            qv[j] = t;
        }
    }
    float Z = 0.f;
    float4 cx[8];
#pragma unroll
    for (int j = 0; j < 8; ++j) cx[j] = make_float4(0.f, 0.f, 0.f, 0.f);

    for (int kb = 0; kb < kcut; kb += 128) {
        int kn = min(128, kcut - kb);
        __syncthreads();
        const float4* Kg = (const float4*)(Km + ((long)(b * SEQL + kb)) * DD + h * DKK);
        const float4* Vg = (const float4*)(Vm + ((long)(b * SEQL + kb)) * DD + h * DKK);
#pragma unroll
        for (int i = 0; i < 8; i++) {
            int idx = i * 128 + tid;
            int r = idx >> 3, c4 = idx & 7;
            if (r < kn) {
                ((float4*)Ks[r])[c4] = Kg[(long)r * (DD / 4) + c4];
                ((float4*)Vs[r])[c4] = Vg[(long)r * (DD / 4) + c4];
            }
        }
        if (tid < kn) dec[tid] = __expf(-tdh * (float)(kb + tid));
        __syncthreads();
        for (int kk = 0; kk < kn; ++kk) {
            const float4* kr = (const float4*)Ks[kk];
            float s0 = 0.f, s1 = 0.f, s2 = 0.f, s3 = 0.f;
#pragma unroll
            for (int j = 0; j < 8; j += 2) {
                float4 k0 = kr[j], k1 = kr[j + 1];
                s0 = fmaf(qv[j].x, k0.x, s0); s1 = fmaf(qv[j].y, k0.y, s1);
                s2 = fmaf(qv[j].z, k0.z, s2); s3 = fmaf(qv[j].w, k0.w, s3);
                s0 = fmaf(qv[j + 1].x, k1.x, s0); s1 = fmaf(qv[j + 1].y, k1.y, s1);
                s2 = fmaf(qv[j + 1].z, k1.z, s2); s3 = fmaf(qv[j + 1].w, k1.w, s3);
            }
            float s = ((s0 + s1) + (s2 + s3)) * dec[kk];
            float e = __expf(s);
            float w = e * e / (1.f + e);
            Z += e;
            const float4* vr = (const float4*)Vs[kk];
#pragma unroll
            for (int j = 0; j < 8; ++j) {
                float4 vv = vr[j];
                cx[j].x = fmaf(w, vv.x, cx[j].x);
                cx[j].y = fmaf(w, vv.y, cx[j].y);
                cx[j].z = fmaf(w, vv.z, cx[j].z);
                cx[j].w = fmaf(w, vv.w, cx[j].w);
            }
        }
    }
    Z += (float)(SEQL - kcut);
    float invZ = 1.f / Z;
    const float4* tv = (const float4*)(tailV + bh * DKK);
    size_t ob = ((size_t)(b * SEQL + q)) * DD + h * DKK;
#pragma unroll
    for (int j = 0; j < 8; ++j) {
        float4 t = tv[j];
        float ov[4];
        ov[0] = (cx[j].x + 0.5f * t.x) * invZ;
        ov[1] = (cx[j].y + 0.5f * t.y) * invZ;
        ov[2] = (cx[j].z + 0.5f * t.z) * invZ;
        ov[3] = (cx[j].w + 0.5f * t.w) * invZ;
#pragma unroll
        for (int u = 0; u < 4; ++u) {
            __nv_bfloat16 hh = __float2bfloat16(ov[u]);
            Ch[ob + j * 4 + u] = hh;
            Cl[ob + j * 4 + u] = __float2bfloat16(ov[u] - __bfloat162float(hh));
        }
    }
}

// ---------------------------------------------------------------- single-query attention (layer 2 last token)
__global__ __launch_bounds__(128)
void attn1_kernel(const float* __restrict__ q2, const float* __restrict__ Km,
                  const float* __restrict__ Vm, const float* __restrict__ td,
                  const float* __restrict__ scale, const float* __restrict__ tailV,
                  float* __restrict__ ctx2, int l) {
    int b = blockIdx.x / HH, h = blockIdx.x % HH;
    int tid = threadIdx.x;
    float tdh = td[l * HH + h];
    int kcut = compute_kcut(tdh);
    float c = scale[l] * rsqrtf((float)DKK);
    __shared__ float qs[DKK];
    __shared__ float ws[128];
    __shared__ float red[4];
    if (tid < DKK) qs[tid] = q2[b * DD + h * DKK + tid] * c;
    __syncthreads();
    float Zp = 0.f;
    float cxd = 0.f;
    for (int kb = 0; kb < kcut; kb += 128) {
        int kn = min(128, kcut - kb);
        float w = 0.f;
        if (tid < kn) {
            int k = kb + tid;
            const float* kr = Km + ((long)(b * SEQL + k)) * DD + h * DKK;
            float s = 0.f;
#pragma unroll
            for (int d = 0; d < DKK; ++d) s = fmaf(qs[d], kr[d], s);
            s *= __expf(-tdh * (float)k);
            float e = __expf(s);
            w = e * e / (1.f + e);
            Zp += e;
        }
        __syncthreads();
        ws[tid] = w;
        __syncthreads();
        if (tid < DKK) {
            for (int kk = 0; kk < kn; ++kk)
                cxd = fmaf(ws[kk], Vm[((long)(b * SEQL + kb + kk)) * DD + h * DKK + tid], cxd);
        }
        __syncthreads();
    }
    float s = Zp;
#pragma unroll
    for (int o = 16; o; o >>= 1) s += __shfl_xor_sync(0xffffffffu, s, o);
    if ((tid & 31) == 0) red[tid >> 5] = s;
    __syncthreads();
    float Z = red[0] + red[1] + red[2] + red[3] + (float)(SEQL - kcut);
    if (tid < DKK)
        ctx2[b * DD + h * DKK + tid] = (cxd + 0.5f * tailV[blockIdx.x * DKK + tid]) / Z;
}

// ---------------------------------------------------------------- small-M GEMM (M=2 rows), fp32
template <bool RELU>
__global__ void rowgemm_kernel(const float* __restrict__ A, long lda,
                               const float* __restrict__ W, const float* __restrict__ bias,
                               float* __restrict__ C, int K, int N) {
    extern __shared__ float arow[];
    int m = blockIdx.x;
    int n = blockIdx.y * blockDim.x + threadIdx.x;
    for (int i = threadIdx.x; i < K; i += blockDim.x) arow[i] = A[(long)m * lda + i];
    __syncthreads();
    float s = bias[n];
    const float* wr = W + (long)n * K;
#pragma unroll 4
    for (int kk = 0; kk < K; ++kk) s = fmaf(arow[kk], wr[kk], s);
    if (RELU) s = fmaxf(s, 0.f);
    C[(long)m * N + n] = s;
}

// ---------------------------------------------------------------- residual + layernorm; optional 2nd partial + bf16 emit
template <bool TWO, bool EMIT>
__global__ void ln_kernel(const float* __restrict__ z, long zs,
                          const float* __restrict__ z2,
                          const float* __restrict__ res, long rs,
                          const float* __restrict__ g, const float* __restrict__ be,
                          float* __restrict__ out, long os,
                          __nv_bfloat16* __restrict__ oh, __nv_bfloat16* __restrict__ ol) {
    int m = blockIdx.x, t = threadIdx.x;
    float v = z[(long)m * zs + t] + res[(long)m * rs + t];
    if (TWO) v += z2[(long)m * zs + t];
    __shared__ float sm[8];
    float s = v;
#pragma unroll
    for (int o = 16; o; o >>= 1) s += __shfl_xor_sync(0xffffffffu, s, o);
    if ((t & 31) == 0) sm[t >> 5] = s;
    __syncthreads();
    float tot = 0.f;
#pragma unroll
    for (int i = 0; i < 8; i++) tot += sm[i];
    float mean = tot * (1.0f / DD);
    float dv = v - mean;
    float s2 = dv * dv;
    __syncthreads();
#pragma unroll
    for (int o = 16; o; o >>= 1) s2 += __shfl_xor_sync(0xffffffffu, s2, o);
    if ((t & 31) == 0) sm[t >> 5] = s2;
    __syncthreads();
    float var = 0.f;
#pragma unroll
    for (int i = 0; i < 8; i++) var += sm[i];
    var *= (1.0f / DD);
    float o = dv * rsqrtf(var + EPSF) * g[t] + be[t];
    out[(long)m * os + t] = o;
    if (EMIT) {
        __nv_bfloat16 hh = __float2bfloat16(o);
        oh[(long)m * DD + t] = hh;
        ol[(long)m * DD + t] = __float2bfloat16(o - __bfloat162float(hh));
    }
}

// ---------------------------------------------------------------- final projection
__global__ void out_kernel(const float* __restrict__ r2, const float* __restrict__ ow,
                           const float* __restrict__ ob, float* __restrict__ out) {
    int b = blockIdx.x, t = threadIdx.x;
    float p = r2[b * DD + t] * ow[t];
    __shared__ float sm[8];
    float s = p;
#pragma unroll
    for (int o = 16; o; o >>= 1) s += __shfl_xor_sync(0xffffffffu, s, o);
    if ((t & 31) == 0) sm[t >> 5] = s;
    __syncthreads();
    if (t == 0) {
        float tot = 0.f;
#pragma unroll
        for (int i = 0; i < 8; i++) tot += sm[i];
        out[b] = 0.5f * tot + ob[0];
    }
}

// ================================================================ host orchestration
extern "C" void kernel_launch(void* const* d_in, const int* in_sizes, int n_in,
                              void* d_out, int out_size) {
    const float* x   = (const float*)d_in[0];
    const float* cw  = (const float*)d_in[1];
    const float* cb  = (const float*)d_in[2];
    const float* bg  = (const float*)d_in[3];
    const float* bbn = (const float*)d_in[4];
    const float* pe  = (const float*)d_in[5];
    const float* qW  = (const float*)d_in[6];
    const float* qb  = (const float*)d_in[7];
    const float* kW  = (const float*)d_in[8];
    const float* kb  = (const float*)d_in[9];
    const float* vW  = (const float*)d_in[10];
    const float* vb  = (const float*)d_in[11];
    const float* oW  = (const float*)d_in[12];
    const float* ob  = (const float*)d_in[13];
    const float* scale = (const float*)d_in[14];
    const float* td  = (const float*)d_in[15];
    const float* ln1g = (const float*)d_in[16];
    const float* ln1b = (const float*)d_in[17];
    const float* f1W = (const float*)d_in[18];
    const float* f1b = (const float*)d_in[19];
    const float* f2W = (const float*)d_in[20];
    const float* f2b = (const float*)d_in[21];
    const float* ln2g = (const float*)d_in[22];
    const float* ln2b = (const float*)d_in[23];
    const float* outW = (const float*)d_in[24];
    const float* outb = (const float*)d_in[25];
    float* out = (float*)d_out;

    float* buf = nullptr;
    cudaGetSymbolAddress((void**)&buf, g_buf);
    float* H0 = buf;
    float* H2 = buf + 1L * NH;
    float* Qb = buf + 2L * NH;
    float* Kb = buf + 3L * NH;
    float* Vb = buf + 4L * NH;
    float* T  = buf + 5L * NH;
    float* TP = buf + 6L * NH;
    __nv_bfloat16* B16 = (__nv_bfloat16*)(buf + 7L * NH);
    __nv_bfloat16* H0h = B16;
    __nv_bfloat16* H0l = B16 + 1L * NH;
    __nv_bfloat16* H2h = B16 + 2L * NH;
    __nv_bfloat16* H2l = B16 + 3L * NH;
    __nv_bfloat16* CXh = B16 + 4L * NH;
    __nv_bfloat16* CXl = B16 + 5L * NH;
    __nv_bfloat16* FFh = B16 + 6L * NH;
    __nv_bfloat16* FFl = B16 + 6L * NH + NFF;
    __nv_bfloat16* Wb  = B16 + 6L * NH + 2L * NFF;
    float* TAIL = buf + 7L * NH + BF16_FLOATS;
    float* SMALL = TAIL + 512;
    float* Q2 = SMALL, *CTX2 = SMALL + 512, *T2 = SMALL + 1024, *R1 = SMALL + 1536;
    float* FFROW = SMALL + 2048, *T3 = SMALL + 4096, *R2 = SMALL + 4608;

    auto WQH = [&](int l){ return Wb + 0       + l * 65536; };
    auto WQL = [&](int l){ return Wb + 131072  + l * 65536; };
    auto WKH = [&](int l){ return Wb + 262144  + l * 65536; };
    auto WKL = [&](int l){ return Wb + 393216  + l * 65536; };
    auto WVH = [&](int l){ return Wb + 524288  + l * 65536; };
    auto WVL = [&](int l){ return Wb + 655360  + l * 65536; };
    auto WOH = [&](int l){ return Wb + 786432  + l * 65536; };
    auto WOL = [&](int l){ return Wb + 917504  + l * 65536; };
    auto WF1H = [&](int l){ return Wb + 1048576 + l * 262144; };
    auto WF1L = [&](int l){ return Wb + 1572864 + l * 262144; };
    auto WF2H = [&](int l){ return Wb + 2097152 + l * 262144; };
    auto WF2L = [&](int l){ return Wb + 2621440 + l * 262144; };

    const int M = BB * SEQL;                 // 4096
    dim3 gAttn(SEQL / 128, BB * HH);

    // --- stem + weight split ---
    conv_pe_kernel<<<(NH + 255) / 256, 256>>>(x, cw, cb, bg, bbn, pe, H0, H0h, H0l);
    wsplit_kernel<<<dim3(128, 1, 6), 256>>>(qW, kW, vW, oW, f1W, f2W, Wb);

    // --- layer 0 QKV (fused z=3) ---
    {
        TcJobs3 J{};
        J.j[0] = {H0h, H0l, WQH(0), WQL(0), qb, Qb, nullptr, nullptr, DD, DD, DD, DD, 2 | 8};
        J.j[1] = {H0h, H0l, WKH(0), WKL(0), kb, Kb, nullptr, nullptr, DD, DD, DD, DD, 2 | 8};
        J.j[2] = {H0h, H0l, WVH(0), WVL(0), vb, Vb, nullptr, nullptr, DD, DD, DD, DD, 2 | 8};
        tc_kernel<<<dim3(DD / 64, M / 128, 3), 256>>>(J);
    }
    tailv_kernel<<<BB * HH, 1024>>>(Vb, td, TAIL, 0);
    attn_kernel<<<gAttn, 128>>>(Qb, Kb, Vb, td, scale, TAIL, CXh, CXl, 0);
    {
        TcJobs3 J{};
        J.j[0] = {CXh, CXl, WOH(0), WOL(0), ob, T, nullptr, nullptr, DD, DD, DD, DD, 2 | 8};
        tc_kernel<<<dim3(DD / 64, M / 128, 1), 256>>>(J);
    }
    ln_kernel<false, true><<<M, 256>>>(T, DD, nullptr, H0, DD, ln1g, ln1b, H2, DD, H2h, H2l);
    {
        TcJobs3 J{};
        J.j[0] = {H2h, H2l, WF1H(0), WF1L(0), f1b, nullptr, FFh, FFl, DD, DD, DFFN, DD, 1 | 4 | 8};
        tc_kernel<<<dim3(DFFN / 64, M / 128, 1), 256>>>(J);
    }
    {   // FFN2 split-K=2 over K=1024; partials T (+bias) and TP
        TcJobs3 J{};
        J.j[0] = {FFh,       FFl,       WF2H(0),       WF2L(0),       f2b, T,  nullptr, nullptr, DFFN, DFFN, DD, 512, 2 | 8};
        J.j[1] = {FFh + 512, FFl + 512, WF2H(0) + 512, WF2L(0) + 512, f2b, TP, nullptr, nullptr, DFFN, DFFN, DD, 512, 2};
        tc_kernel<<<dim3(DD / 64, M / 128, 2), 256>>>(J);
    }
    ln_kernel<true, true><<<M, 256>>>(T, DD, TP, H2, DD, ln2g, ln2b, H0, DD, H0h, H0l);

    // --- layer 1 (only last token needed downstream of attention) ---
    const float* qW1 = qW + DD * DD;   const float* qb1 = qb + DD;
    const float* oW1 = oW + DD * DD;   const float* ob1 = ob + DD;
    const float* kb1 = kb + DD;        const float* vb1 = vb + DD;
    const float* ln1g1 = ln1g + DD;    const float* ln1b1 = ln1b + DD;
    const float* ln2g1 = ln2g + DD;    const float* ln2b1 = ln2b + DD;
    const float* f1W1 = f1W + DFFN * DD; const float* f1b1 = f1b + DFFN;
    const float* f2W1 = f2W + DD * DFFN; const float* f2b1 = f2b + DD;
    const float* hlast = H0 + (long)(SEQL - 1) * DD;

    {
        TcJobs3 J{};
        J.j[0] = {H0h, H0l, WKH(1), WKL(1), kb1, Kb, nullptr, nullptr, DD, DD, DD, DD, 2 | 8};
        J.j[1] = {H0h, H0l, WVH(1), WVL(1), vb1, Vb, nullptr, nullptr, DD, DD, DD, DD, 2 | 8};
        tc_kernel<<<dim3(DD / 64, M / 128, 2), 256>>>(J);
    }
    tailv_kernel<<<BB * HH, 1024>>>(Vb, td, TAIL, 1);

    rowgemm_kernel<false><<<dim3(BB, 1), 256, DD * 4>>>(hlast, (long)SEQL * DD, qW1, qb1, Q2, DD, DD);
    attn1_kernel<<<BB * HH, 128>>>(Q2, Kb, Vb, td, scale, TAIL, CTX2, 1);
    rowgemm_kernel<false><<<dim3(BB, 1), 256, DD * 4>>>(CTX2, DD, oW1, ob1, T2, DD, DD);
    ln_kernel<false, false><<<BB, 256>>>(T2, DD, nullptr, hlast, (long)SEQL * DD, ln1g1, ln1b1, R1, DD, nullptr, nullptr);
    rowgemm_kernel<true ><<<dim3(BB, DFFN / 256), 256, DD * 4>>>(R1, DD, f1W1, f1b1, FFROW, DD, DFFN);
    rowgemm_kernel<false><<<dim3(BB, 1), 256, DFFN * 4>>>(FFROW, DFFN, f2W1, f2b1, T3, DFFN, DD);
    ln_kernel<false, false><<<BB, 256>>>(T3, DD, nullptr, R1, DD, ln2g1, ln2b1, R2, DD, nullptr, nullptr);

    out_kernel<<<BB, 256>>>(R2, outW, outb, out);
}